// round 15
// baseline (speedup 1.0000x reference)
#include <cuda_runtime.h>

#define NCLASS 6
#define THREADS 1024
#define MAXB 256

__device__ int g_presence[MAXB];
__device__ int g_done = 0;

__global__ void __launch_bounds__(THREADS)
se_loss_kernel(const float* __restrict__ se_pred,
               const int4* __restrict__ target,   // 4 x int32 per load
               float* __restrict__ out,
               int B, int nv_per_batch /* int4 vectors per batch */)
{
    __shared__ int smask;
    __shared__ int sdone;
    __shared__ float ssum[THREADS / 32];

    const int tid   = threadIdx.x;
    const int batch = blockIdx.x;

    if (tid == 0) { smask = 0; sdone = 0; }
    __syncthreads();

    const int4* base = target + (size_t)batch * nv_per_batch;
    const int niter = (nv_per_batch + THREADS - 1) / THREADS;

    int mask = 0;
    for (int it = 0; it < niter; ++it) {
        int i = it * THREADS + tid;
        if (i < nv_per_batch) {
            int4 v = base[i];                       // LDG.E.128, coalesced
            mask |= (1 << v.x) | (1 << v.y) | (1 << v.z) | (1 << v.w);
        }
        // fold this tile's bits into the block mask
        int wm = __reduce_or_sync(0xffffffffu, mask);
        if ((tid & 31) == 0) atomicOr(&smask, wm);
        __syncthreads();
        if (tid == 0) sdone = (smask == 0x3F);      // all 6 classes seen
        __syncthreads();
        if (sdone) break;                            // uniform break
    }

    // publish this batch's presence mask; count finished blocks
    __shared__ int s_is_last;
    if (tid == 0) {
        g_presence[batch] = smask;
        __threadfence();
        int old = atomicAdd(&g_done, 1);
        s_is_last = (old == gridDim.x - 1);
    }
    __syncthreads();
    if (!s_is_last) return;

    // ---- last block: BCE(mean) over [B, NCLASS] ----
    const int total = B * NCLASS;
    float local = 0.0f;
    for (int i = tid; i < total; i += THREADS) {
        int b = i / NCLASS;
        int c = i - b * NCLASS;
        int pv = *((volatile int*)&g_presence[b]);   // bypass stale reg cache
        float t = (float)((pv >> c) & 1);
        float p = se_pred[i];
        float lp  = fmaxf(logf(p),     -100.0f);
        float l1p = fmaxf(log1pf(-p),  -100.0f);
        local -= t * lp + (1.0f - t) * l1p;
    }
    #pragma unroll
    for (int o = 16; o > 0; o >>= 1)
        local += __shfl_down_sync(0xffffffffu, local, o);
    if ((tid & 31) == 0) ssum[tid >> 5] = local;
    __syncthreads();
    if (tid < 32) {
        float v = (tid < THREADS / 32) ? ssum[tid] : 0.0f;
        #pragma unroll
        for (int o = 16; o > 0; o >>= 1)
            v += __shfl_down_sync(0xffffffffu, v, o);
        if (tid == 0) {
            out[0] = v / (float)total;
            g_done = 0;                              // reset for next graph replay
        }
    }
}

extern "C" void kernel_launch(void* const* d_in, const int* in_sizes, int n_in,
                              void* d_out, int out_size)
{
    const float* se_pred = (const float*)d_in[0];   // [B, 6] f32
    const int4*  target  = (const int4*)d_in[1];    // [B, H, W] int32

    int B = in_sizes[0] / NCLASS;                   // 64
    long long n_i32 = (long long)in_sizes[1];       // B*H*W int32 elements
    int nv_per_batch = (int)(n_i32 / B / 4);        // int4 vectors per batch

    se_loss_kernel<<<B, THREADS>>>(se_pred, target, (float*)d_out,
                                   B, nv_per_batch);
}

// round 16
// speedup vs baseline: 1.3495x; 1.3495x over previous
#include <cuda_runtime.h>

#define NCLASS 6
#define MAXB 256
#define UNROLL 8   // int4 loads per lane per iteration -> 32*8*4 = 1024 samples/iter

__device__ float g_partial[MAXB];
__device__ int   g_done = 0;

__global__ void __launch_bounds__(32)
se_loss_kernel(const float* __restrict__ se_pred,
               const int4* __restrict__ target,   // 4 x int32 per load
               float* __restrict__ out,
               int B, int nv_per_batch /* int4 vectors per batch */)
{
    const int lane  = threadIdx.x;      // 0..31
    const int batch = blockIdx.x;

    // Preload this batch's se_pred row concurrently with the first target loads.
    float p = (lane < NCLASS) ? se_pred[batch * NCLASS + lane] : 0.5f;

    const int4* base = target + (size_t)batch * nv_per_batch;
    const int per_iter = 32 * UNROLL;
    const int niter = (nv_per_batch + per_iter - 1) / per_iter;

    int mask = 0;
    for (int it = 0; it < niter; ++it) {
        int i0 = it * per_iter + lane;
        #pragma unroll
        for (int u = 0; u < UNROLL; ++u) {
            int i = i0 + u * 32;                 // coalesced 512B segments
            if (i < nv_per_batch) {
                int4 v = base[i];                // LDG.E.128
                mask |= (1 << v.x) | (1 << v.y) | (1 << v.z) | (1 << v.w);
            }
        }
        int wm = __reduce_or_sync(0xffffffffu, mask);
        if (wm == 0x3F) { mask = wm; break; }    // all 6 classes seen
        mask = wm;
    }

    // BCE terms for THIS batch (6 lanes), summed within the warp.
    float term = 0.0f;
    if (lane < NCLASS) {
        float t   = (float)((mask >> lane) & 1);
        float lp  = fmaxf(logf(p),    -100.0f);
        float l1p = fmaxf(log1pf(-p), -100.0f);
        term = -(t * lp + (1.0f - t) * l1p);
    }
    #pragma unroll
    for (int o = 16; o > 0; o >>= 1)
        term += __shfl_down_sync(0xffffffffu, term, o);

    // Publish partial, count finished blocks.
    int is_last = 0;
    if (lane == 0) {
        g_partial[batch] = term;
        __threadfence();
        int old = atomicAdd(&g_done, 1);
        is_last = (old == gridDim.x - 1);
    }
    is_last = __shfl_sync(0xffffffffu, is_last, 0);
    if (!is_last) return;

    // Last block: deterministic fixed-order sum of 64 partials (L2-hot).
    float s = 0.0f;
    for (int b = lane; b < B; b += 32)
        s += *((volatile float*)&g_partial[b]);
    #pragma unroll
    for (int o = 16; o > 0; o >>= 1)
        s += __shfl_down_sync(0xffffffffu, s, o);
    if (lane == 0) {
        out[0] = s / (float)(B * NCLASS);
        g_done = 0;                              // reset for next graph replay
    }
}

extern "C" void kernel_launch(void* const* d_in, const int* in_sizes, int n_in,
                              void* d_out, int out_size)
{
    const float* se_pred = (const float*)d_in[0];   // [B, 6] f32
    const int4*  target  = (const int4*)d_in[1];    // [B, H, W] int32

    int B = in_sizes[0] / NCLASS;                   // 64
    long long n_i32 = (long long)in_sizes[1];       // B*H*W int32 elements
    int nv_per_batch = (int)(n_i32 / B / 4);        // int4 vectors per batch

    se_loss_kernel<<<B, 32>>>(se_pred, target, (float*)d_out, B, nv_per_batch);
}